// round 6
// baseline (speedup 1.0000x reference)
#include <cuda_runtime.h>
#include <cuda_bf16.h>
#include <math.h>
#include <stdint.h>

// ----------------------------------------------------------------------------
// Problem constants
// ----------------------------------------------------------------------------
#define BATCH  2
#define SEQ    2048
#define DIM    1024
#define HEADS  16
#define DHEAD  64
#define INNER  1024
#define ROWS   (BATCH * SEQ)        // 4096
#define GK     1024                 // GEMM K (always 1024 here)
#define QKV_N  3072                 // fused q|k|v width
#define ATT_SCALE 0.125f

// Scratch (device globals — no allocation allowed in kernel_launch)
__device__ float g_xn   [ROWS * DIM];         // layernormed x (tf32-rounded)
__device__ float g_qkv  [ROWS * QKV_N];       // q|k|v projections (fp32)
__device__ float g_attn [ROWS * INNER];       // attention out (tf32-rounded)
__device__ float g_wqkvT[QKV_N * DIM];        // [wq|wkv]^T  [3072,1024] tf32
__device__ float g_woutT[DIM * INNER];        // w_out^T [N,K] tf32

// ----------------------------------------------------------------------------
// Helpers
// ----------------------------------------------------------------------------
__device__ __forceinline__ uint32_t smem_u32(const void* p) {
    uint32_t a;
    asm("{ .reg .u64 t; cvta.to.shared.u64 t, %1; cvt.u32.u64 %0, t; }"
        : "=r"(a) : "l"(p));
    return a;
}
__device__ __forceinline__ float to_tf32(float x) {
    float r;
    asm("cvt.rna.tf32.f32 %0, %1;" : "=f"(r) : "f"(x));
    return r;
}

#define CP_ASYNC16(dst, src) \
    asm volatile("cp.async.cg.shared.global [%0], [%1], 16;" \
                 :: "r"(dst), "l"(src) : "memory")
#define CP_COMMIT() asm volatile("cp.async.commit_group;" ::: "memory")
#define CP_WAIT(n)  asm volatile("cp.async.wait_group %0;" :: "n"(n) : "memory")

// m16n8k8 tf32 mma: D += A*B (row.col), fp32 accum
__device__ __forceinline__ void mma_tf32(float* d, const uint32_t* a,
                                         const uint32_t* b) {
    asm volatile(
        "mma.sync.aligned.m16n8k8.row.col.f32.tf32.tf32.f32 "
        "{%0,%1,%2,%3}, {%4,%5,%6,%7}, {%8,%9}, {%0,%1,%2,%3};"
        : "+f"(d[0]), "+f"(d[1]), "+f"(d[2]), "+f"(d[3])
        : "r"(a[0]), "r"(a[1]), "r"(a[2]), "r"(a[3]), "r"(b[0]), "r"(b[1]));
}

// GEMM-tile swizzle (32-float rows, float4 XOR)
__device__ __forceinline__ uint32_t lds_sw(const float* base, int row, int kf) {
    int idx = row * 32 + ((((kf >> 2) ^ (row & 7)) << 2) | (kf & 3));
    return __float_as_uint(base[idx]);
}

// Attention-tile swizzle: [row][64] tiles, addr = row*64 + (col ^ swz(row))
__device__ __forceinline__ int att_swz(int row) {
    return ((row & 3) << 3) | (row & 4);
}

// ----------------------------------------------------------------------------
// LayerNorm (tf32-rounded output)
// ----------------------------------------------------------------------------
__global__ void ln_kernel(const float* __restrict__ x,
                          const float* __restrict__ gamma,
                          const float* __restrict__ beta,
                          float* __restrict__ xn) {
    int row = blockIdx.x;
    int t   = threadIdx.x;
    const float* xr = x + (size_t)row * DIM;

    float4 v = *(const float4*)&xr[t * 4];
    float s  = v.x + v.y + v.z + v.w;
    float s2 = v.x*v.x + v.y*v.y + v.z*v.z + v.w*v.w;
    #pragma unroll
    for (int o = 16; o; o >>= 1) {
        s  += __shfl_xor_sync(0xffffffffu, s,  o);
        s2 += __shfl_xor_sync(0xffffffffu, s2, o);
    }
    __shared__ float sh1[8], sh2[8];
    int w = t >> 5, l = t & 31;
    if (l == 0) { sh1[w] = s; sh2[w] = s2; }
    __syncthreads();
    float ts = 0.f, ts2 = 0.f;
    #pragma unroll
    for (int i = 0; i < 8; i++) { ts += sh1[i]; ts2 += sh2[i]; }

    float mean = ts * (1.0f / DIM);
    float var  = ts2 * (1.0f / DIM) - mean * mean;
    float rstd = rsqrtf(var + 1e-5f);

    float4 g  = *(const float4*)&gamma[t * 4];
    float4 bb = *(const float4*)&beta[t * 4];
    float4 o;
    o.x = to_tf32((v.x - mean) * rstd * g.x + bb.x);
    o.y = to_tf32((v.y - mean) * rstd * g.y + bb.y);
    o.z = to_tf32((v.z - mean) * rstd * g.z + bb.z);
    o.w = to_tf32((v.w - mean) * rstd * g.w + bb.w);
    *(float4*)&xn[(size_t)row * DIM + t * 4] = o;
}

// ----------------------------------------------------------------------------
// Transpose + tf32 round: Wt[n,k] = tf32(W[k,n]).  W is [K, N].
// ----------------------------------------------------------------------------
__global__ void transpose_tf32_kernel(const float* __restrict__ W,
                                      float* __restrict__ Wt, int K, int N) {
    __shared__ float tile[32][33];
    int n0 = blockIdx.x * 32, k0 = blockIdx.y * 32;
    int tx = threadIdx.x, ty = threadIdx.y;
    #pragma unroll
    for (int i = ty; i < 32; i += 8)
        tile[i][tx] = W[(size_t)(k0 + i) * N + n0 + tx];
    __syncthreads();
    #pragma unroll
    for (int i = ty; i < 32; i += 8)
        Wt[(size_t)(n0 + i) * K + k0 + tx] = to_tf32(tile[tx][i]);
}

// ----------------------------------------------------------------------------
// tf32 mma.sync GEMM: C = A @ Bt^T (+bias)
// 128x128 CTA, 256 threads (8 warps, 4m x 2n). K-chunk 32.
// 3-stage cp.async pipeline, ONE __syncthreads per chunk.
// ----------------------------------------------------------------------------
#define GEMM_SMEM_FLOATS (6 * 4096)   // 3 stages x (A 128x32 + B 128x32)
#define CHUNKS (GK / 32)

__global__ __launch_bounds__(256)
void gemm_mma_kernel(const float* __restrict__ A,
                     const float* __restrict__ Bt,
                     float* __restrict__ C,
                     const float* __restrict__ bias,
                     int N) {
    extern __shared__ float smg[];
    float* sA[3] = { smg,          smg + 4096,  smg + 8192 };
    float* sB[3] = { smg + 12288,  smg + 16384, smg + 20480 };
    uint32_t uA[3] = { smem_u32(sA[0]), smem_u32(sA[1]), smem_u32(sA[2]) };
    uint32_t uB[3] = { smem_u32(sB[0]), smem_u32(sB[1]), smem_u32(sB[2]) };

    int t    = threadIdx.x;
    int lane = t & 31;
    int wid  = t >> 5;
    int wm   = wid >> 1;
    int wn   = wid & 1;
    int gid  = lane >> 2;
    int tig  = lane & 3;
    int bm   = blockIdx.y * 128;
    int bn   = blockIdx.x * 128;

    const float* Ag = A  + (size_t)bm * GK;
    const float* Bg = Bt + (size_t)bn * GK;

    float acc[2][8][4];
    #pragma unroll
    for (int mt = 0; mt < 2; mt++)
        #pragma unroll
        for (int nt = 0; nt < 8; nt++)
            #pragma unroll
            for (int i = 0; i < 4; i++) acc[mt][nt][i] = 0.f;

    auto load_chunk = [&](int c, int s) {
        int k0 = c * 32;
        #pragma unroll
        for (int i = 0; i < 4; ++i) {
            int idx = t + i * 256;
            int row = idx >> 3, qq = idx & 7;
            uint32_t d = uA[s] + (uint32_t)((row * 32 + ((qq ^ (row & 7)) << 2)) * 4);
            CP_ASYNC16(d, Ag + (size_t)row * GK + k0 + qq * 4);
        }
        #pragma unroll
        for (int i = 0; i < 4; ++i) {
            int idx = t + i * 256;
            int row = idx >> 3, qq = idx & 7;
            uint32_t d = uB[s] + (uint32_t)((row * 32 + ((qq ^ (row & 7)) << 2)) * 4);
            CP_ASYNC16(d, Bg + (size_t)row * GK + k0 + qq * 4);
        }
        CP_COMMIT();
    };

    load_chunk(0, 0);
    load_chunk(1, 1);

    for (int c = 0; c < CHUNKS; ++c) {
        int s = c % 3;
        // need chunk c complete; at most one newer commit (chunk c+1) in flight
        if (c == CHUNKS - 1) { CP_WAIT(0); } else { CP_WAIT(1); }
        __syncthreads();
        // Prefetch chunk c+2 into the stage freed at iteration c-1.
        // Safe: every warp passed the barrier above only after finishing
        // its reads of stage (c-1)%3 == (c+2)%3.
        if (c + 2 < CHUNKS) load_chunk(c + 2, (c + 2) % 3);

        const float* a_s = sA[s];
        const float* b_s = sB[s];
        #pragma unroll
        for (int g = 0; g < 4; ++g) {
            uint32_t af[2][4];
            #pragma unroll
            for (int mt = 0; mt < 2; mt++) {
                int r = wm * 32 + mt * 16 + gid;
                af[mt][0] = lds_sw(a_s, r,     g * 8 + tig);
                af[mt][1] = lds_sw(a_s, r + 8, g * 8 + tig);
                af[mt][2] = lds_sw(a_s, r,     g * 8 + tig + 4);
                af[mt][3] = lds_sw(a_s, r + 8, g * 8 + tig + 4);
            }
            uint32_t bf[8][2];
            #pragma unroll
            for (int nt = 0; nt < 8; nt++) {
                int n = wn * 64 + nt * 8 + gid;
                bf[nt][0] = lds_sw(b_s, n, g * 8 + tig);
                bf[nt][1] = lds_sw(b_s, n, g * 8 + tig + 4);
            }
            #pragma unroll
            for (int mt = 0; mt < 2; mt++)
                #pragma unroll
                for (int nt = 0; nt < 8; nt++)
                    mma_tf32(acc[mt][nt], af[mt], bf[nt]);
        }
    }

    #pragma unroll
    for (int mt = 0; mt < 2; mt++) {
        int r0 = bm + wm * 32 + mt * 16 + gid;
        #pragma unroll
        for (int nt = 0; nt < 8; nt++) {
            int cc = bn + wn * 64 + nt * 8 + tig * 2;
            float b0 = bias ? bias[cc]     : 0.f;
            float b1 = bias ? bias[cc + 1] : 0.f;
            *(float2*)&C[(size_t)r0 * N + cc] =
                make_float2(acc[mt][nt][0] + b0, acc[mt][nt][1] + b1);
            *(float2*)&C[(size_t)(r0 + 8) * N + cc] =
                make_float2(acc[mt][nt][2] + b0, acc[mt][nt][3] + b1);
        }
    }
}

// ----------------------------------------------------------------------------
// Flash attention on tensor cores (mma.sync tf32).
// Reads fused qkv buffer: row stride 3072; q at col 0, k at 1024, v at 2048.
// ----------------------------------------------------------------------------
#define ATTN_SMEM_FLOATS (8192 + 4096 + 4096 + 8192)   // 96 KB

__global__ __launch_bounds__(128) void attn_mma_kernel(
    const float* __restrict__ qkv, float* __restrict__ o) {
    extern __shared__ float sma[];
    float* Qs = sma;              // [128][64]
    float* Ks = Qs + 8192;        // [64][64]
    float* Vs = Ks + 4096;        // [64][64]
    float* Ps = Vs + 4096;        // [128][64]

    int bh = blockIdx.y;
    int b  = bh >> 4, h = bh & 15;
    int q0 = blockIdx.x * 128;
    int t  = threadIdx.x;
    int lane = t & 31, w = t >> 5;
    int gid = lane >> 2, tig = lane & 3;
    int wm  = w * 32;
    int swzg = att_swz(gid);

    // Load Q tile once: scale + tf32 round, swizzled store
    #pragma unroll
    for (int i = 0; i < 16; i++) {
        int idx = i * 128 + t;
        int r = idx >> 4, qc = idx & 15;
        float4 v = *(const float4*)&qkv[((size_t)(b * SEQ + q0 + r)) * QKV_N
                                        + h * DHEAD + qc * 4];
        int c4 = qc ^ (att_swz(r) >> 2);
        float* p = &Qs[r * 64 + c4 * 4];
        p[0] = to_tf32(v.x * ATT_SCALE);
        p[1] = to_tf32(v.y * ATT_SCALE);
        p[2] = to_tf32(v.z * ATT_SCALE);
        p[3] = to_tf32(v.w * ATT_SCALE);
    }

    float m_[2][2], l_[2][2], oacc[2][8][4];
    #pragma unroll
    for (int mt = 0; mt < 2; mt++)
        #pragma unroll
        for (int hf = 0; hf < 2; hf++) { m_[mt][hf] = -1e30f; l_[mt][hf] = 0.f; }
    #pragma unroll
    for (int mt = 0; mt < 2; mt++)
        #pragma unroll
        for (int nt = 0; nt < 8; nt++)
            #pragma unroll
            for (int i = 0; i < 4; i++) oacc[mt][nt][i] = 0.f;

    for (int j0 = 0; j0 < SEQ; j0 += 64) {
        __syncthreads();
        // Load K and V tiles (64 rows x 64), tf32-rounded, swizzled
        #pragma unroll
        for (int i = 0; i < 8; i++) {
            int idx = i * 128 + t;
            int r = idx >> 4, qc = idx & 15;
            size_t gb = ((size_t)(b * SEQ + j0 + r)) * QKV_N
                        + INNER + h * DHEAD + qc * 4;
            float4 kk = *(const float4*)&qkv[gb];
            float4 vv = *(const float4*)&qkv[gb + INNER];
            int c4 = qc ^ (att_swz(r) >> 2);
            float* pk = &Ks[r * 64 + c4 * 4];
            pk[0] = to_tf32(kk.x); pk[1] = to_tf32(kk.y);
            pk[2] = to_tf32(kk.z); pk[3] = to_tf32(kk.w);
            float* pv = &Vs[r * 64 + c4 * 4];
            pv[0] = to_tf32(vv.x); pv[1] = to_tf32(vv.y);
            pv[2] = to_tf32(vv.z); pv[3] = to_tf32(vv.w);
        }
        __syncthreads();

        // S = (Q*scale) @ K^T
        float sacc[2][8][4];
        #pragma unroll
        for (int mt = 0; mt < 2; mt++)
            #pragma unroll
            for (int nt = 0; nt < 8; nt++)
                #pragma unroll
                for (int i = 0; i < 4; i++) sacc[mt][nt][i] = 0.f;

        #pragma unroll
        for (int g = 0; g < 8; g++) {
            int kc = g * 8;
            uint32_t a[2][4];
            #pragma unroll
            for (int mt = 0; mt < 2; mt++) {
                int r0 = wm + mt * 16 + gid;
                a[mt][0] = __float_as_uint(Qs[r0 * 64       + ((kc + tig)     ^ swzg)]);
                a[mt][1] = __float_as_uint(Qs[(r0 + 8) * 64 + ((kc + tig)     ^ swzg)]);
                a[mt][2] = __float_as_uint(Qs[r0 * 64       + ((kc + tig + 4) ^ swzg)]);
                a[mt][3] = __float_as_uint(Qs[(r0 + 8) * 64 + ((kc + tig + 4) ^ swzg)]);
            }
            #pragma unroll
            for (int nt = 0; nt < 8; nt++) {
                int nr = nt * 8 + gid;
                uint32_t bf[2];
                bf[0] = __float_as_uint(Ks[nr * 64 + ((kc + tig)     ^ swzg)]);
                bf[1] = __float_as_uint(Ks[nr * 64 + ((kc + tig + 4) ^ swzg)]);
                mma_tf32(sacc[0][nt], a[0], bf);
                mma_tf32(sacc[1][nt], a[1], bf);
            }
        }

        // Online softmax in accumulator layout
        #pragma unroll
        for (int mt = 0; mt < 2; mt++) {
            #pragma unroll
            for (int hf = 0; hf < 2; hf++) {
                float mx = -1e30f;
                #pragma unroll
                for (int nt = 0; nt < 8; nt++) {
                    mx = fmaxf(mx, sacc[mt][nt][hf * 2]);
                    mx = fmaxf(mx, sacc[mt][nt][hf * 2 + 1]);
                }
                mx = fmaxf(mx, __shfl_xor_sync(0xffffffffu, mx, 1));
                mx = fmaxf(mx, __shfl_xor_sync(0xffffffffu, mx, 2));
                float mn = fmaxf(m_[mt][hf], mx);
                float alpha = __expf(m_[mt][hf] - mn);
                m_[mt][hf] = mn;
                float rs = 0.f;
                #pragma unroll
                for (int nt = 0; nt < 8; nt++) {
                    float p0 = to_tf32(__expf(sacc[mt][nt][hf * 2]     - mn));
                    float p1 = to_tf32(__expf(sacc[mt][nt][hf * 2 + 1] - mn));
                    sacc[mt][nt][hf * 2]     = p0;
                    sacc[mt][nt][hf * 2 + 1] = p1;
                    rs += p0 + p1;
                }
                rs += __shfl_xor_sync(0xffffffffu, rs, 1);
                rs += __shfl_xor_sync(0xffffffffu, rs, 2);
                l_[mt][hf] = l_[mt][hf] * alpha + rs;
                #pragma unroll
                for (int nt = 0; nt < 8; nt++) {
                    oacc[mt][nt][hf * 2]     *= alpha;
                    oacc[mt][nt][hf * 2 + 1] *= alpha;
                }
            }
        }

        // Stage P to smem
        #pragma unroll
        for (int mt = 0; mt < 2; mt++) {
            int r0 = wm + mt * 16 + gid;
            #pragma unroll
            for (int nt = 0; nt < 8; nt++) {
                int c = (nt * 8 + tig * 2) ^ swzg;
                *(float2*)&Ps[r0 * 64 + c] =
                    make_float2(sacc[mt][nt][0], sacc[mt][nt][1]);
                *(float2*)&Ps[(r0 + 8) * 64 + c] =
                    make_float2(sacc[mt][nt][2], sacc[mt][nt][3]);
            }
        }
        __syncthreads();

        // O += P @ V
        #pragma unroll
        for (int g = 0; g < 8; g++) {
            int kc = g * 8;
            uint32_t a[2][4];
            #pragma unroll
            for (int mt = 0; mt < 2; mt++) {
                int r0 = wm + mt * 16 + gid;
                a[mt][0] = __float_as_uint(Ps[r0 * 64       + ((kc + tig)     ^ swzg)]);
                a[mt][1] = __float_as_uint(Ps[(r0 + 8) * 64 + ((kc + tig)     ^ swzg)]);
                a[mt][2] = __float_as_uint(Ps[r0 * 64       + ((kc + tig + 4) ^ swzg)]);
                a[mt][3] = __float_as_uint(Ps[(r0 + 8) * 64 + ((kc + tig + 4) ^ swzg)]);
            }
            int kr0 = (kc + tig) * 64;
            int kr1 = (kc + tig + 4) * 64;
            int sv0 = tig << 3, sv1 = (tig << 3) | 4;
            #pragma unroll
            for (int nt = 0; nt < 8; nt++) {
                int d0 = nt * 8 + gid;
                uint32_t bf[2];
                bf[0] = __float_as_uint(Vs[kr0 + (d0 ^ sv0)]);
                bf[1] = __float_as_uint(Vs[kr1 + (d0 ^ sv1)]);
                mma_tf32(oacc[0][nt], a[0], bf);
                mma_tf32(oacc[1][nt], a[1], bf);
            }
        }
    }

    // Epilogue: normalize, tf32-round, store
    #pragma unroll
    for (int mt = 0; mt < 2; mt++) {
        float inv0 = 1.f / l_[mt][0];
        float inv1 = 1.f / l_[mt][1];
        int r0 = q0 + wm + mt * 16 + gid;
        #pragma unroll
        for (int nt = 0; nt < 8; nt++) {
            int cc = h * DHEAD + nt * 8 + tig * 2;
            *(float2*)&o[((size_t)(b * SEQ + r0)) * INNER + cc] =
                make_float2(to_tf32(oacc[mt][nt][0] * inv0),
                            to_tf32(oacc[mt][nt][1] * inv0));
            *(float2*)&o[((size_t)(b * SEQ + r0 + 8)) * INNER + cc] =
                make_float2(to_tf32(oacc[mt][nt][2] * inv1),
                            to_tf32(oacc[mt][nt][3] * inv1));
        }
    }
}

// ----------------------------------------------------------------------------
// Launch
// ----------------------------------------------------------------------------
extern "C" void kernel_launch(void* const* d_in, const int* in_sizes, int n_in,
                              void* d_out, int out_size) {
    const float* x     = (const float*)d_in[0];
    const float* w_q   = (const float*)d_in[1];
    const float* w_kv  = (const float*)d_in[2];
    const float* w_out = (const float*)d_in[3];
    const float* b_out = (const float*)d_in[4];
    const float* gamma = (const float*)d_in[5];
    const float* beta  = (const float*)d_in[6];
    float* out = (float*)d_out;

    void *p_xn, *p_qkv, *p_attn, *p_wqkvT, *p_woutT;
    cudaGetSymbolAddress(&p_xn,    g_xn);
    cudaGetSymbolAddress(&p_qkv,   g_qkv);
    cudaGetSymbolAddress(&p_attn,  g_attn);
    cudaGetSymbolAddress(&p_wqkvT, g_wqkvT);
    cudaGetSymbolAddress(&p_woutT, g_woutT);
    float* xn    = (float*)p_xn;
    float* qkv   = (float*)p_qkv;
    float* attn  = (float*)p_attn;
    float* wqkvT = (float*)p_wqkvT;
    float* woutT = (float*)p_woutT;

    const int attn_smem = ATTN_SMEM_FLOATS * (int)sizeof(float);  // 98304
    const int gemm_smem = GEMM_SMEM_FLOATS * (int)sizeof(float);  // 98304
    cudaFuncSetAttribute(attn_mma_kernel,
                         cudaFuncAttributeMaxDynamicSharedMemorySize, attn_smem);
    cudaFuncSetAttribute(gemm_mma_kernel,
                         cudaFuncAttributeMaxDynamicSharedMemorySize, gemm_smem);

    // 0) Weight transposes (+ tf32 rounding) into fused wqkvT
    transpose_tf32_kernel<<<dim3(INNER/32,   DIM/32), dim3(32, 8)>>>(
        w_q,  wqkvT,                DIM, INNER);
    transpose_tf32_kernel<<<dim3(2*INNER/32, DIM/32), dim3(32, 8)>>>(
        w_kv, wqkvT + INNER * DIM,  DIM, 2*INNER);
    transpose_tf32_kernel<<<dim3(DIM/32,   INNER/32), dim3(32, 8)>>>(
        w_out, woutT, INNER, DIM);

    // 1) LayerNorm (tf32-rounded output)
    ln_kernel<<<ROWS, 256>>>(x, gamma, beta, xn);

    // 2) Fused QKV projection (mma.sync tf32), N = 3072
    gemm_mma_kernel<<<dim3(QKV_N/128, ROWS/128), 256, gemm_smem>>>(
        xn, wqkvT, qkv, nullptr, QKV_N);

    // 3) Flash attention (mma.sync tf32) on fused qkv
    attn_mma_kernel<<<dim3(SEQ/128, BATCH*HEADS), 128, attn_smem>>>(qkv, attn);

    // 4) Output projection + bias (mma.sync tf32)
    gemm_mma_kernel<<<dim3(DIM/128, ROWS/128), 256, gemm_smem>>>(
        attn, woutT, out, b_out, DIM);
}

// round 7
// speedup vs baseline: 1.1872x; 1.1872x over previous
#include <cuda_runtime.h>
#include <cuda_bf16.h>
#include <math.h>
#include <stdint.h>

// ----------------------------------------------------------------------------
// Problem constants
// ----------------------------------------------------------------------------
#define BATCH  2
#define SEQ    2048
#define DIM    1024
#define HEADS  16
#define DHEAD  64
#define INNER  1024
#define ROWS   (BATCH * SEQ)        // 4096
#define GK     1024                 // GEMM K (always 1024 here)
#define QKV_N  3072                 // fused q|k|v width
#define ATT_SCALE 0.125f

// Scratch (device globals — no allocation allowed in kernel_launch)
__device__ float g_xn   [ROWS * DIM];         // layernormed x (tf32-rounded)
__device__ float g_qkv  [ROWS * QKV_N];       // q|k|v projections (fp32)
__device__ float g_attn [ROWS * INNER];       // attention out (tf32-rounded)
__device__ float g_wqkvT[QKV_N * DIM];        // [wq|wkv]^T  [3072,1024] tf32
__device__ float g_woutT[DIM * INNER];        // w_out^T [N,K] tf32

// ----------------------------------------------------------------------------
// Helpers
// ----------------------------------------------------------------------------
__device__ __forceinline__ uint32_t smem_u32(const void* p) {
    uint32_t a;
    asm("{ .reg .u64 t; cvta.to.shared.u64 t, %1; cvt.u32.u64 %0, t; }"
        : "=r"(a) : "l"(p));
    return a;
}
__device__ __forceinline__ float to_tf32(float x) {
    float r;
    asm("cvt.rna.tf32.f32 %0, %1;" : "=f"(r) : "f"(x));
    return r;
}

#define CP_ASYNC16(dst, src) \
    asm volatile("cp.async.cg.shared.global [%0], [%1], 16;" \
                 :: "r"(dst), "l"(src) : "memory")
#define CP_COMMIT() asm volatile("cp.async.commit_group;" ::: "memory")
#define CP_WAIT(n)  asm volatile("cp.async.wait_group %0;" :: "n"(n) : "memory")

// m16n8k8 tf32 mma: D += A*B (row.col), fp32 accum
__device__ __forceinline__ void mma_tf32(float* d, const uint32_t* a,
                                         const uint32_t* b) {
    asm volatile(
        "mma.sync.aligned.m16n8k8.row.col.f32.tf32.tf32.f32 "
        "{%0,%1,%2,%3}, {%4,%5,%6,%7}, {%8,%9}, {%0,%1,%2,%3};"
        : "+f"(d[0]), "+f"(d[1]), "+f"(d[2]), "+f"(d[3])
        : "r"(a[0]), "r"(a[1]), "r"(a[2]), "r"(a[3]), "r"(b[0]), "r"(b[1]));
}

// GEMM-tile swizzle (32-float rows, float4 XOR)
__device__ __forceinline__ uint32_t lds_sw(const float* base, int row, int kf) {
    int idx = row * 32 + ((((kf >> 2) ^ (row & 7)) << 2) | (kf & 3));
    return __float_as_uint(base[idx]);
}

// Attention-tile swizzle: [row][64] tiles, addr = row*64 + (col ^ swz(row))
__device__ __forceinline__ int att_swz(int row) {
    return ((row & 3) << 3) | (row & 4);
}

// ----------------------------------------------------------------------------
// LayerNorm (tf32-rounded output)
// ----------------------------------------------------------------------------
__global__ void ln_kernel(const float* __restrict__ x,
                          const float* __restrict__ gamma,
                          const float* __restrict__ beta,
                          float* __restrict__ xn) {
    int row = blockIdx.x;
    int t   = threadIdx.x;
    const float* xr = x + (size_t)row * DIM;

    float4 v = *(const float4*)&xr[t * 4];
    float s  = v.x + v.y + v.z + v.w;
    float s2 = v.x*v.x + v.y*v.y + v.z*v.z + v.w*v.w;
    #pragma unroll
    for (int o = 16; o; o >>= 1) {
        s  += __shfl_xor_sync(0xffffffffu, s,  o);
        s2 += __shfl_xor_sync(0xffffffffu, s2, o);
    }
    __shared__ float sh1[8], sh2[8];
    int w = t >> 5, l = t & 31;
    if (l == 0) { sh1[w] = s; sh2[w] = s2; }
    __syncthreads();
    float ts = 0.f, ts2 = 0.f;
    #pragma unroll
    for (int i = 0; i < 8; i++) { ts += sh1[i]; ts2 += sh2[i]; }

    float mean = ts * (1.0f / DIM);
    float var  = ts2 * (1.0f / DIM) - mean * mean;
    float rstd = rsqrtf(var + 1e-5f);

    float4 g  = *(const float4*)&gamma[t * 4];
    float4 bb = *(const float4*)&beta[t * 4];
    float4 o;
    o.x = to_tf32((v.x - mean) * rstd * g.x + bb.x);
    o.y = to_tf32((v.y - mean) * rstd * g.y + bb.y);
    o.z = to_tf32((v.z - mean) * rstd * g.z + bb.z);
    o.w = to_tf32((v.w - mean) * rstd * g.w + bb.w);
    *(float4*)&xn[(size_t)row * DIM + t * 4] = o;
}

// ----------------------------------------------------------------------------
// Transpose + tf32 round: Wt[n,k] = tf32(W[k,n]).  W is [K, N].
// ----------------------------------------------------------------------------
__global__ void transpose_tf32_kernel(const float* __restrict__ W,
                                      float* __restrict__ Wt, int K, int N) {
    __shared__ float tile[32][33];
    int n0 = blockIdx.x * 32, k0 = blockIdx.y * 32;
    int tx = threadIdx.x, ty = threadIdx.y;
    #pragma unroll
    for (int i = ty; i < 32; i += 8)
        tile[i][tx] = W[(size_t)(k0 + i) * N + n0 + tx];
    __syncthreads();
    #pragma unroll
    for (int i = ty; i < 32; i += 8)
        Wt[(size_t)(n0 + i) * K + k0 + tx] = to_tf32(tile[tx][i]);
}

// ----------------------------------------------------------------------------
// tf32 mma.sync GEMM: C = A @ Bt^T (+bias)
// 128x128 CTA, 128 threads = 4 warps in 2x2, warp tile 64x64.
// K-chunk 32, 2-stage cp.async pipeline (R5-proven scheme).
// Per k8-step per warp: 32 LDS.32 for 32 mmas (1.0 LDS/mma).
// ----------------------------------------------------------------------------
#define GEMM_SMEM_FLOATS (4 * 4096)   // 2 stages x (A 128x32 + B 128x32) = 64KB
#define CHUNKS (GK / 32)

__global__ __launch_bounds__(128)
void gemm_mma_kernel(const float* __restrict__ A,
                     const float* __restrict__ Bt,
                     float* __restrict__ C,
                     const float* __restrict__ bias,
                     int N) {
    extern __shared__ float smg[];
    float* sA[2] = { smg,         smg + 4096 };
    float* sB[2] = { smg + 8192,  smg + 12288 };
    uint32_t uA[2] = { smem_u32(sA[0]), smem_u32(sA[1]) };
    uint32_t uB[2] = { smem_u32(sB[0]), smem_u32(sB[1]) };

    int t    = threadIdx.x;
    int lane = t & 31;
    int wid  = t >> 5;            // 0..3
    int wm   = (wid >> 1) * 64;   // 0 or 64
    int wn   = (wid & 1) * 64;    // 0 or 64
    int gid  = lane >> 2;
    int tig  = lane & 3;
    int bm   = blockIdx.y * 128;
    int bn   = blockIdx.x * 128;

    const float* Ag = A  + (size_t)bm * GK;
    const float* Bg = Bt + (size_t)bn * GK;

    float acc[4][8][4];
    #pragma unroll
    for (int mt = 0; mt < 4; mt++)
        #pragma unroll
        for (int nt = 0; nt < 8; nt++)
            #pragma unroll
            for (int i = 0; i < 4; i++) acc[mt][nt][i] = 0.f;

    // chunk loader: 8 cp.async for A + 8 for B per thread (128 threads)
    auto load_chunk = [&](int c, int s) {
        int k0 = c * 32;
        #pragma unroll
        for (int i = 0; i < 8; ++i) {
            int idx = t + i * 128;            // 0..1023
            int row = idx >> 3, qq = idx & 7;
            uint32_t d = uA[s] + (uint32_t)((row * 32 + ((qq ^ (row & 7)) << 2)) * 4);
            CP_ASYNC16(d, Ag + (size_t)row * GK + k0 + qq * 4);
        }
        #pragma unroll
        for (int i = 0; i < 8; ++i) {
            int idx = t + i * 128;
            int row = idx >> 3, qq = idx & 7;
            uint32_t d = uB[s] + (uint32_t)((row * 32 + ((qq ^ (row & 7)) << 2)) * 4);
            CP_ASYNC16(d, Bg + (size_t)row * GK + k0 + qq * 4);
        }
        CP_COMMIT();
    };

    load_chunk(0, 0);
    load_chunk(1, 1);

    for (int c = 0; c < CHUNKS; ++c) {
        int s = c & 1;
        if (c == CHUNKS - 1) { CP_WAIT(0); } else { CP_WAIT(1); }
        __syncthreads();

        const float* a_s = sA[s];
        const float* b_s = sB[s];
        #pragma unroll
        for (int g = 0; g < 4; ++g) {
            uint32_t af[4][4];
            #pragma unroll
            for (int mt = 0; mt < 4; mt++) {
                int r = wm + mt * 16 + gid;
                af[mt][0] = lds_sw(a_s, r,     g * 8 + tig);
                af[mt][1] = lds_sw(a_s, r + 8, g * 8 + tig);
                af[mt][2] = lds_sw(a_s, r,     g * 8 + tig + 4);
                af[mt][3] = lds_sw(a_s, r + 8, g * 8 + tig + 4);
            }
            uint32_t bf[8][2];
            #pragma unroll
            for (int nt = 0; nt < 8; nt++) {
                int n = wn + nt * 8 + gid;
                bf[nt][0] = lds_sw(b_s, n, g * 8 + tig);
                bf[nt][1] = lds_sw(b_s, n, g * 8 + tig + 4);
            }
            #pragma unroll
            for (int mt = 0; mt < 4; mt++)
                #pragma unroll
                for (int nt = 0; nt < 8; nt++)
                    mma_tf32(acc[mt][nt], af[mt], bf[nt]);
        }
        __syncthreads();
        if (c + 2 < CHUNKS) load_chunk(c + 2, s);
    }

    // Epilogue
    #pragma unroll
    for (int mt = 0; mt < 4; mt++) {
        int r0 = bm + wm + mt * 16 + gid;
        #pragma unroll
        for (int nt = 0; nt < 8; nt++) {
            int cc = bn + wn + nt * 8 + tig * 2;
            float b0 = bias ? bias[cc]     : 0.f;
            float b1 = bias ? bias[cc + 1] : 0.f;
            *(float2*)&C[(size_t)r0 * N + cc] =
                make_float2(acc[mt][nt][0] + b0, acc[mt][nt][1] + b1);
            *(float2*)&C[(size_t)(r0 + 8) * N + cc] =
                make_float2(acc[mt][nt][2] + b0, acc[mt][nt][3] + b1);
        }
    }
}

// ----------------------------------------------------------------------------
// Flash attention on tensor cores (mma.sync tf32) — unchanged from R5/R6.
// Reads fused qkv buffer: row stride 3072; q at col 0, k at 1024, v at 2048.
// ----------------------------------------------------------------------------
#define ATTN_SMEM_FLOATS (8192 + 4096 + 4096 + 8192)   // 96 KB

__global__ __launch_bounds__(128) void attn_mma_kernel(
    const float* __restrict__ qkv, float* __restrict__ o) {
    extern __shared__ float sma[];
    float* Qs = sma;              // [128][64]
    float* Ks = Qs + 8192;        // [64][64]
    float* Vs = Ks + 4096;        // [64][64]
    float* Ps = Vs + 4096;        // [128][64]

    int bh = blockIdx.y;
    int b  = bh >> 4, h = bh & 15;
    int q0 = blockIdx.x * 128;
    int t  = threadIdx.x;
    int lane = t & 31, w = t >> 5;
    int gid = lane >> 2, tig = lane & 3;
    int wm  = w * 32;
    int swzg = att_swz(gid);

    // Load Q tile once: scale + tf32 round, swizzled store
    #pragma unroll
    for (int i = 0; i < 16; i++) {
        int idx = i * 128 + t;
        int r = idx >> 4, qc = idx & 15;
        float4 v = *(const float4*)&qkv[((size_t)(b * SEQ + q0 + r)) * QKV_N
                                        + h * DHEAD + qc * 4];
        int c4 = qc ^ (att_swz(r) >> 2);
        float* p = &Qs[r * 64 + c4 * 4];
        p[0] = to_tf32(v.x * ATT_SCALE);
        p[1] = to_tf32(v.y * ATT_SCALE);
        p[2] = to_tf32(v.z * ATT_SCALE);
        p[3] = to_tf32(v.w * ATT_SCALE);
    }

    float m_[2][2], l_[2][2], oacc[2][8][4];
    #pragma unroll
    for (int mt = 0; mt < 2; mt++)
        #pragma unroll
        for (int hf = 0; hf < 2; hf++) { m_[mt][hf] = -1e30f; l_[mt][hf] = 0.f; }
    #pragma unroll
    for (int mt = 0; mt < 2; mt++)
        #pragma unroll
        for (int nt = 0; nt < 8; nt++)
            #pragma unroll
            for (int i = 0; i < 4; i++) oacc[mt][nt][i] = 0.f;

    for (int j0 = 0; j0 < SEQ; j0 += 64) {
        __syncthreads();
        // Load K and V tiles (64 rows x 64), tf32-rounded, swizzled
        #pragma unroll
        for (int i = 0; i < 8; i++) {
            int idx = i * 128 + t;
            int r = idx >> 4, qc = idx & 15;
            size_t gb = ((size_t)(b * SEQ + j0 + r)) * QKV_N
                        + INNER + h * DHEAD + qc * 4;
            float4 kk = *(const float4*)&qkv[gb];
            float4 vv = *(const float4*)&qkv[gb + INNER];
            int c4 = qc ^ (att_swz(r) >> 2);
            float* pk = &Ks[r * 64 + c4 * 4];
            pk[0] = to_tf32(kk.x); pk[1] = to_tf32(kk.y);
            pk[2] = to_tf32(kk.z); pk[3] = to_tf32(kk.w);
            float* pv = &Vs[r * 64 + c4 * 4];
            pv[0] = to_tf32(vv.x); pv[1] = to_tf32(vv.y);
            pv[2] = to_tf32(vv.z); pv[3] = to_tf32(vv.w);
        }
        __syncthreads();

        // S = (Q*scale) @ K^T
        float sacc[2][8][4];
        #pragma unroll
        for (int mt = 0; mt < 2; mt++)
            #pragma unroll
            for (int nt = 0; nt < 8; nt++)
                #pragma unroll
                for (int i = 0; i < 4; i++) sacc[mt][nt][i] = 0.f;

        #pragma unroll
        for (int g = 0; g < 8; g++) {
            int kc = g * 8;
            uint32_t a[2][4];
            #pragma unroll
            for (int mt = 0; mt < 2; mt++) {
                int r0 = wm + mt * 16 + gid;
                a[mt][0] = __float_as_uint(Qs[r0 * 64       + ((kc + tig)     ^ swzg)]);
                a[mt][1] = __float_as_uint(Qs[(r0 + 8) * 64 + ((kc + tig)     ^ swzg)]);
                a[mt][2] = __float_as_uint(Qs[r0 * 64       + ((kc + tig + 4) ^ swzg)]);
                a[mt][3] = __float_as_uint(Qs[(r0 + 8) * 64 + ((kc + tig + 4) ^ swzg)]);
            }
            #pragma unroll
            for (int nt = 0; nt < 8; nt++) {
                int nr = nt * 8 + gid;
                uint32_t bf[2];
                bf[0] = __float_as_uint(Ks[nr * 64 + ((kc + tig)     ^ swzg)]);
                bf[1] = __float_as_uint(Ks[nr * 64 + ((kc + tig + 4) ^ swzg)]);
                mma_tf32(sacc[0][nt], a[0], bf);
                mma_tf32(sacc[1][nt], a[1], bf);
            }
        }

        // Online softmax in accumulator layout
        #pragma unroll
        for (int mt = 0; mt < 2; mt++) {
            #pragma unroll
            for (int hf = 0; hf < 2; hf++) {
                float mx = -1e30f;
                #pragma unroll
                for (int nt = 0; nt < 8; nt++) {
                    mx = fmaxf(mx, sacc[mt][nt][hf * 2]);
                    mx = fmaxf(mx, sacc[mt][nt][hf * 2 + 1]);
                }
                mx = fmaxf(mx, __shfl_xor_sync(0xffffffffu, mx, 1));
                mx = fmaxf(mx, __shfl_xor_sync(0xffffffffu, mx, 2));
                float mn = fmaxf(m_[mt][hf], mx);
                float alpha = __expf(m_[mt][hf] - mn);
                m_[mt][hf] = mn;
                float rs = 0.f;
                #pragma unroll
                for (int nt = 0; nt < 8; nt++) {
                    float p0 = to_tf32(__expf(sacc[mt][nt][hf * 2]     - mn));
                    float p1 = to_tf32(__expf(sacc[mt][nt][hf * 2 + 1] - mn));
                    sacc[mt][nt][hf * 2]     = p0;
                    sacc[mt][nt][hf * 2 + 1] = p1;
                    rs += p0 + p1;
                }
                rs += __shfl_xor_sync(0xffffffffu, rs, 1);
                rs += __shfl_xor_sync(0xffffffffu, rs, 2);
                l_[mt][hf] = l_[mt][hf] * alpha + rs;
                #pragma unroll
                for (int nt = 0; nt < 8; nt++) {
                    oacc[mt][nt][hf * 2]     *= alpha;
                    oacc[mt][nt][hf * 2 + 1] *= alpha;
                }
            }
        }

        // Stage P to smem
        #pragma unroll
        for (int mt = 0; mt < 2; mt++) {
            int r0 = wm + mt * 16 + gid;
            #pragma unroll
            for (int nt = 0; nt < 8; nt++) {
                int c = (nt * 8 + tig * 2) ^ swzg;
                *(float2*)&Ps[r0 * 64 + c] =
                    make_float2(sacc[mt][nt][0], sacc[mt][nt][1]);
                *(float2*)&Ps[(r0 + 8) * 64 + c] =
                    make_float2(sacc[mt][nt][2], sacc[mt][nt][3]);
            }
        }
        __syncthreads();

        // O += P @ V
        #pragma unroll
        for (int g = 0; g < 8; g++) {
            int kc = g * 8;
            uint32_t a[2][4];
            #pragma unroll
            for (int mt = 0; mt < 2; mt++) {
                int r0 = wm + mt * 16 + gid;
                a[mt][0] = __float_as_uint(Ps[r0 * 64       + ((kc + tig)     ^ swzg)]);
                a[mt][1] = __float_as_uint(Ps[(r0 + 8) * 64 + ((kc + tig)     ^ swzg)]);
                a[mt][2] = __float_as_uint(Ps[r0 * 64       + ((kc + tig + 4) ^ swzg)]);
                a[mt][3] = __float_as_uint(Ps[(r0 + 8) * 64 + ((kc + tig + 4) ^ swzg)]);
            }
            int kr0 = (kc + tig) * 64;
            int kr1 = (kc + tig + 4) * 64;
            int sv0 = tig << 3, sv1 = (tig << 3) | 4;
            #pragma unroll
            for (int nt = 0; nt < 8; nt++) {
                int d0 = nt * 8 + gid;
                uint32_t bf[2];
                bf[0] = __float_as_uint(Vs[kr0 + (d0 ^ sv0)]);
                bf[1] = __float_as_uint(Vs[kr1 + (d0 ^ sv1)]);
                mma_tf32(oacc[0][nt], a[0], bf);
                mma_tf32(oacc[1][nt], a[1], bf);
            }
        }
    }

    // Epilogue: normalize, tf32-round, store
    #pragma unroll
    for (int mt = 0; mt < 2; mt++) {
        float inv0 = 1.f / l_[mt][0];
        float inv1 = 1.f / l_[mt][1];
        int r0 = q0 + wm + mt * 16 + gid;
        #pragma unroll
        for (int nt = 0; nt < 8; nt++) {
            int cc = h * DHEAD + nt * 8 + tig * 2;
            *(float2*)&o[((size_t)(b * SEQ + r0)) * INNER + cc] =
                make_float2(to_tf32(oacc[mt][nt][0] * inv0),
                            to_tf32(oacc[mt][nt][1] * inv0));
            *(float2*)&o[((size_t)(b * SEQ + r0 + 8)) * INNER + cc] =
                make_float2(to_tf32(oacc[mt][nt][2] * inv1),
                            to_tf32(oacc[mt][nt][3] * inv1));
        }
    }
}

// ----------------------------------------------------------------------------
// Launch
// ----------------------------------------------------------------------------
extern "C" void kernel_launch(void* const* d_in, const int* in_sizes, int n_in,
                              void* d_out, int out_size) {
    const float* x     = (const float*)d_in[0];
    const float* w_q   = (const float*)d_in[1];
    const float* w_kv  = (const float*)d_in[2];
    const float* w_out = (const float*)d_in[3];
    const float* b_out = (const float*)d_in[4];
    const float* gamma = (const float*)d_in[5];
    const float* beta  = (const float*)d_in[6];
    float* out = (float*)d_out;

    void *p_xn, *p_qkv, *p_attn, *p_wqkvT, *p_woutT;
    cudaGetSymbolAddress(&p_xn,    g_xn);
    cudaGetSymbolAddress(&p_qkv,   g_qkv);
    cudaGetSymbolAddress(&p_attn,  g_attn);
    cudaGetSymbolAddress(&p_wqkvT, g_wqkvT);
    cudaGetSymbolAddress(&p_woutT, g_woutT);
    float* xn    = (float*)p_xn;
    float* qkv   = (float*)p_qkv;
    float* attn  = (float*)p_attn;
    float* wqkvT = (float*)p_wqkvT;
    float* woutT = (float*)p_woutT;

    const int attn_smem = ATTN_SMEM_FLOATS * (int)sizeof(float);  // 98304
    const int gemm_smem = GEMM_SMEM_FLOATS * (int)sizeof(float);  // 65536
    cudaFuncSetAttribute(attn_mma_kernel,
                         cudaFuncAttributeMaxDynamicSharedMemorySize, attn_smem);
    cudaFuncSetAttribute(gemm_mma_kernel,
                         cudaFuncAttributeMaxDynamicSharedMemorySize, gemm_smem);

    // 0) Weight transposes (+ tf32 rounding) into fused wqkvT
    transpose_tf32_kernel<<<dim3(INNER/32,   DIM/32), dim3(32, 8)>>>(
        w_q,  wqkvT,                DIM, INNER);
    transpose_tf32_kernel<<<dim3(2*INNER/32, DIM/32), dim3(32, 8)>>>(
        w_kv, wqkvT + INNER * DIM,  DIM, 2*INNER);
    transpose_tf32_kernel<<<dim3(DIM/32,   INNER/32), dim3(32, 8)>>>(
        w_out, woutT, INNER, DIM);

    // 1) LayerNorm (tf32-rounded output)
    ln_kernel<<<ROWS, 256>>>(x, gamma, beta, xn);

    // 2) Fused QKV projection (mma.sync tf32), N = 3072
    gemm_mma_kernel<<<dim3(QKV_N/128, ROWS/128), 128, gemm_smem>>>(
        xn, wqkvT, qkv, nullptr, QKV_N);

    // 3) Flash attention (mma.sync tf32) on fused qkv
    attn_mma_kernel<<<dim3(SEQ/128, BATCH*HEADS), 128, attn_smem>>>(qkv, attn);

    // 4) Output projection + bias (mma.sync tf32)
    gemm_mma_kernel<<<dim3(DIM/128, ROWS/128), 128, gemm_smem>>>(
        attn, woutT, out, b_out, DIM);
}

// round 8
// speedup vs baseline: 2.6368x; 2.2210x over previous
#include <cuda_runtime.h>
#include <cuda_fp16.h>
#include <math.h>
#include <stdint.h>

// ----------------------------------------------------------------------------
// Problem constants
// ----------------------------------------------------------------------------
#define BATCH  2
#define SEQ    2048
#define DIM    1024
#define HEADS  16
#define DHEAD  64
#define INNER  1024
#define ROWS   (BATCH * SEQ)        // 4096
#define GK     1024
#define QKV_N  3072
#define ATT_SCALE 0.125f

// Scratch (device globals)
__device__ __half g_xn   [ROWS * DIM];        // layernormed x (fp16)
__device__ __half g_qkv  [ROWS * QKV_N];      // q|k|v (fp16; q pre-scaled)
__device__ __half g_attn [ROWS * INNER];      // attention out (fp16)
__device__ __half g_wqkvT[QKV_N * DIM];       // [wq*scale|wkv]^T (fp16)
__device__ __half g_woutT[DIM * INNER];       // w_out^T (fp16)

// ----------------------------------------------------------------------------
// Helpers
// ----------------------------------------------------------------------------
__device__ __forceinline__ uint32_t smem_u32(const void* p) {
    uint32_t a;
    asm("{ .reg .u64 t; cvta.to.shared.u64 t, %1; cvt.u32.u64 %0, t; }"
        : "=r"(a) : "l"(p));
    return a;
}

#define CP_ASYNC16(dst, src) \
    asm volatile("cp.async.cg.shared.global [%0], [%1], 16;" \
                 :: "r"(dst), "l"(src) : "memory")
#define CP_COMMIT() asm volatile("cp.async.commit_group;" ::: "memory")
#define CP_WAIT(n)  asm volatile("cp.async.wait_group %0;" :: "n"(n) : "memory")

#define LDSM_X4(r0, r1, r2, r3, addr) \
    asm volatile("ldmatrix.sync.aligned.m8n8.x4.shared.b16 {%0,%1,%2,%3}, [%4];" \
                 : "=r"(r0), "=r"(r1), "=r"(r2), "=r"(r3) : "r"(addr))
#define LDSM_X4_T(r0, r1, r2, r3, addr) \
    asm volatile("ldmatrix.sync.aligned.m8n8.x4.trans.shared.b16 {%0,%1,%2,%3}, [%4];" \
                 : "=r"(r0), "=r"(r1), "=r"(r2), "=r"(r3) : "r"(addr))

// m16n8k16 fp16 mma, fp32 accumulate
__device__ __forceinline__ void mma_f16(float* d, const uint32_t* a,
                                        const uint32_t* b) {
    asm volatile(
        "mma.sync.aligned.m16n8k16.row.col.f32.f16.f16.f32 "
        "{%0,%1,%2,%3}, {%4,%5,%6,%7}, {%8,%9}, {%0,%1,%2,%3};"
        : "+f"(d[0]), "+f"(d[1]), "+f"(d[2]), "+f"(d[3])
        : "r"(a[0]), "r"(a[1]), "r"(a[2]), "r"(a[3]), "r"(b[0]), "r"(b[1]));
}

// Tiles: rows of 64 halves (128 B). 16B-chunk swizzle: chunk' = chunk ^ (row&7).
__device__ __forceinline__ uint32_t tile_off(int row, int chunk) {
    return (uint32_t)(row * 128 + ((chunk ^ (row & 7)) << 4));
}

// ----------------------------------------------------------------------------
// LayerNorm (fp16 output)
// ----------------------------------------------------------------------------
__global__ void ln_kernel(const float* __restrict__ x,
                          const float* __restrict__ gamma,
                          const float* __restrict__ beta,
                          __half* __restrict__ xn) {
    int row = blockIdx.x;
    int t   = threadIdx.x;
    const float* xr = x + (size_t)row * DIM;

    float4 v = *(const float4*)&xr[t * 4];
    float s  = v.x + v.y + v.z + v.w;
    float s2 = v.x*v.x + v.y*v.y + v.z*v.z + v.w*v.w;
    #pragma unroll
    for (int o = 16; o; o >>= 1) {
        s  += __shfl_xor_sync(0xffffffffu, s,  o);
        s2 += __shfl_xor_sync(0xffffffffu, s2, o);
    }
    __shared__ float sh1[8], sh2[8];
    int w = t >> 5, l = t & 31;
    if (l == 0) { sh1[w] = s; sh2[w] = s2; }
    __syncthreads();
    float ts = 0.f, ts2 = 0.f;
    #pragma unroll
    for (int i = 0; i < 8; i++) { ts += sh1[i]; ts2 += sh2[i]; }

    float mean = ts * (1.0f / DIM);
    float var  = ts2 * (1.0f / DIM) - mean * mean;
    float rstd = rsqrtf(var + 1e-5f);

    float4 g  = *(const float4*)&gamma[t * 4];
    float4 bb = *(const float4*)&beta[t * 4];
    __half2 h01 = __floats2half2_rn((v.x - mean) * rstd * g.x + bb.x,
                                    (v.y - mean) * rstd * g.y + bb.y);
    __half2 h23 = __floats2half2_rn((v.z - mean) * rstd * g.z + bb.z,
                                    (v.w - mean) * rstd * g.w + bb.w);
    uint2 pk;
    pk.x = *(uint32_t*)&h01;
    pk.y = *(uint32_t*)&h23;
    *(uint2*)&xn[(size_t)row * DIM + t * 4] = pk;
}

// ----------------------------------------------------------------------------
// Transpose + fp16 round (+scale): Wt[n,k] = half(W[k,n]*scale)
// ----------------------------------------------------------------------------
__global__ void transpose_f16_kernel(const float* __restrict__ W,
                                     __half* __restrict__ Wt, int K, int N,
                                     float scale) {
    __shared__ float tile[32][33];
    int n0 = blockIdx.x * 32, k0 = blockIdx.y * 32;
    int tx = threadIdx.x, ty = threadIdx.y;
    #pragma unroll
    for (int i = ty; i < 32; i += 8)
        tile[i][tx] = W[(size_t)(k0 + i) * N + n0 + tx];
    __syncthreads();
    #pragma unroll
    for (int i = ty; i < 32; i += 8)
        Wt[(size_t)(n0 + i) * K + k0 + tx] = __float2half_rn(tile[tx][i] * scale);
}

// ----------------------------------------------------------------------------
// fp16 mma GEMM: C[M,N](+bias) = A[M,1024] @ Bt[N,1024]^T
// 128x128 CTA, 128 threads (4 warps 2x2, warp tile 64x64).
// K-chunk 64 halves, 2-stage cp.async pipeline, ldmatrix.x4 fragments.
// Writes half (Ch) or float (Cf) — exactly one is non-null.
// ----------------------------------------------------------------------------
#define GEMM_SMEM (4 * 16384)   // A0 A1 B0 B1, each 128x64 halves = 16KB
#define CHUNKS (GK / 64)        // 16

__global__ __launch_bounds__(128)
void gemm_f16_kernel(const __half* __restrict__ A,
                     const __half* __restrict__ Bt,
                     __half* __restrict__ Ch,
                     float* __restrict__ Cf,
                     const float* __restrict__ bias,
                     int N) {
    extern __shared__ char smg[];
    uint32_t base = smem_u32(smg);
    uint32_t uA[2] = { base,          base + 16384u };
    uint32_t uB[2] = { base + 32768u, base + 49152u };

    int t    = threadIdx.x;
    int lane = t & 31;
    int wid  = t >> 5;
    int wm   = (wid >> 1) * 64;
    int wn   = (wid & 1) * 64;
    int gid  = lane >> 2;
    int tig  = lane & 3;
    int bsel = lane >> 3;       // ldmatrix block select 0..3
    int lrow = lane & 7;
    int bm   = blockIdx.y * 128;
    int bn   = blockIdx.x * 128;

    const __half* Ag = A  + (size_t)bm * GK;
    const __half* Bg = Bt + (size_t)bn * GK;

    float acc[4][8][4];
    #pragma unroll
    for (int mt = 0; mt < 4; mt++)
        #pragma unroll
        for (int nt = 0; nt < 8; nt++)
            #pragma unroll
            for (int i = 0; i < 4; i++) acc[mt][nt][i] = 0.f;

    auto load_chunk = [&](int c, int s) {
        int k0 = c * 64;
        #pragma unroll
        for (int i = 0; i < 8; ++i) {
            int idx = t + i * 128;          // 0..1023
            int row = idx >> 3, q = idx & 7;
            CP_ASYNC16(uA[s] + tile_off(row, q),
                       Ag + (size_t)row * GK + k0 + q * 8);
        }
        #pragma unroll
        for (int i = 0; i < 8; ++i) {
            int idx = t + i * 128;
            int row = idx >> 3, q = idx & 7;
            CP_ASYNC16(uB[s] + tile_off(row, q),
                       Bg + (size_t)row * GK + k0 + q * 8);
        }
        CP_COMMIT();
    };

    load_chunk(0, 0);
    load_chunk(1, 1);

    for (int c = 0; c < CHUNKS; ++c) {
        int s = c & 1;
        if (c == CHUNKS - 1) { CP_WAIT(0); } else { CP_WAIT(1); }
        __syncthreads();

        #pragma unroll
        for (int g = 0; g < 4; ++g) {       // k16 steps within chunk
            uint32_t af[4][4];
            #pragma unroll
            for (int mt = 0; mt < 4; mt++) {
                int row = wm + mt * 16 + ((bsel & 1) << 3) + lrow;
                int ch  = g * 2 + (bsel >> 1);
                LDSM_X4(af[mt][0], af[mt][1], af[mt][2], af[mt][3],
                        uA[s] + tile_off(row, ch));
            }
            uint32_t bf[8][2];
            #pragma unroll
            for (int np = 0; np < 4; np++) {
                int nrow = wn + ((2 * np + (bsel >> 1)) << 3) + lrow;
                int ch   = g * 2 + (bsel & 1);
                uint32_t r0, r1, r2, r3;
                LDSM_X4(r0, r1, r2, r3, uB[s] + tile_off(nrow, ch));
                bf[2*np][0] = r0;  bf[2*np][1] = r1;
                bf[2*np+1][0] = r2; bf[2*np+1][1] = r3;
            }
            #pragma unroll
            for (int mt = 0; mt < 4; mt++)
                #pragma unroll
                for (int nt = 0; nt < 8; nt++)
                    mma_f16(acc[mt][nt], af[mt], bf[nt]);
        }
        __syncthreads();
        if (c + 2 < CHUNKS) load_chunk(c + 2, s);
    }

    // Epilogue
    #pragma unroll
    for (int mt = 0; mt < 4; mt++) {
        int r0 = bm + wm + mt * 16 + gid;
        #pragma unroll
        for (int nt = 0; nt < 8; nt++) {
            int cc = bn + wn + nt * 8 + tig * 2;
            float b0 = bias ? bias[cc]     : 0.f;
            float b1 = bias ? bias[cc + 1] : 0.f;
            if (Ch) {
                *(__half2*)&Ch[(size_t)r0 * N + cc] =
                    __floats2half2_rn(acc[mt][nt][0] + b0, acc[mt][nt][1] + b1);
                *(__half2*)&Ch[(size_t)(r0 + 8) * N + cc] =
                    __floats2half2_rn(acc[mt][nt][2] + b0, acc[mt][nt][3] + b1);
            } else {
                *(float2*)&Cf[(size_t)r0 * N + cc] =
                    make_float2(acc[mt][nt][0] + b0, acc[mt][nt][1] + b1);
                *(float2*)&Cf[(size_t)(r0 + 8) * N + cc] =
                    make_float2(acc[mt][nt][2] + b0, acc[mt][nt][3] + b1);
            }
        }
    }
}

// ----------------------------------------------------------------------------
// Flash attention, fp16 mma (m16n8k16). CTA: 128 q-rows x one (b,h);
// 128 threads = 4 warps (m32 bands). 64-key tiles. Q pre-scaled.
// Smem (48KB): Qs[128][64]h, Ks[64][64]h, Vs[64][64]h (key-major,
// transposed at read via ldmatrix.trans), Ps[128][64]h.
// ----------------------------------------------------------------------------
#define ATTN_SMEM 49152

__global__ __launch_bounds__(128) void attn_f16_kernel(
    const __half* __restrict__ qkv, __half* __restrict__ o) {
    extern __shared__ char sma[];
    uint32_t uQ = smem_u32(sma);
    uint32_t uK = uQ + 16384u;
    uint32_t uV = uQ + 24576u;
    uint32_t uP = uQ + 32768u;

    int bh = blockIdx.y;
    int b  = bh >> 4, h = bh & 15;
    int q0 = blockIdx.x * 128;
    int t  = threadIdx.x;
    int lane = t & 31, w = t >> 5;
    int gid = lane >> 2, tig = lane & 3;
    int bsel = lane >> 3, lrow = lane & 7;
    int wm  = w * 32;

    // Load Q tile (pure copy; scale folded into w_q)
    #pragma unroll
    for (int i = 0; i < 8; i++) {
        int idx = i * 128 + t;
        int r = idx >> 3, q = idx & 7;
        *(uint4*)(sma + tile_off(r, q)) =
            *(const uint4*)(qkv + ((size_t)(b * SEQ + q0 + r)) * QKV_N
                            + h * DHEAD + q * 8);
    }

    float m_[2][2], l_[2][2], oacc[2][8][4];
    #pragma unroll
    for (int mt = 0; mt < 2; mt++)
        #pragma unroll
        for (int hf = 0; hf < 2; hf++) { m_[mt][hf] = -1e30f; l_[mt][hf] = 0.f; }
    #pragma unroll
    for (int mt = 0; mt < 2; mt++)
        #pragma unroll
        for (int nt = 0; nt < 8; nt++)
            #pragma unroll
            for (int i = 0; i < 4; i++) oacc[mt][nt][i] = 0.f;

    for (int j0 = 0; j0 < SEQ; j0 += 64) {
        __syncthreads();
        // Load K and V (both key-major copies)
        #pragma unroll
        for (int i = 0; i < 4; i++) {
            int idx = i * 128 + t;
            int r = idx >> 3, q = idx & 7;
            size_t gb = ((size_t)(b * SEQ + j0 + r)) * QKV_N + h * DHEAD + q * 8;
            uint32_t off = tile_off(r, q);
            *(uint4*)(sma + 16384 + off) = *(const uint4*)(qkv + gb + INNER);
            *(uint4*)(sma + 24576 + off) = *(const uint4*)(qkv + gb + 2 * INNER);
        }
        __syncthreads();

        // S = Q @ K^T
        float sacc[2][8][4];
        #pragma unroll
        for (int mt = 0; mt < 2; mt++)
            #pragma unroll
            for (int nt = 0; nt < 8; nt++)
                #pragma unroll
                for (int i = 0; i < 4; i++) sacc[mt][nt][i] = 0.f;

        #pragma unroll
        for (int g = 0; g < 4; g++) {
            uint32_t aq[2][4];
            #pragma unroll
            for (int mt = 0; mt < 2; mt++) {
                int row = wm + mt * 16 + ((bsel & 1) << 3) + lrow;
                int ch  = g * 2 + (bsel >> 1);
                LDSM_X4(aq[mt][0], aq[mt][1], aq[mt][2], aq[mt][3],
                        uQ + tile_off(row, ch));
            }
            uint32_t bk[8][2];
            #pragma unroll
            for (int np = 0; np < 4; np++) {
                int nrow = ((2 * np + (bsel >> 1)) << 3) + lrow;
                int ch   = g * 2 + (bsel & 1);
                uint32_t r0, r1, r2, r3;
                LDSM_X4(r0, r1, r2, r3, uK + tile_off(nrow, ch));
                bk[2*np][0] = r0;  bk[2*np][1] = r1;
                bk[2*np+1][0] = r2; bk[2*np+1][1] = r3;
            }
            #pragma unroll
            for (int mt = 0; mt < 2; mt++)
                #pragma unroll
                for (int nt = 0; nt < 8; nt++)
                    mma_f16(sacc[mt][nt], aq[mt], bk[nt]);
        }

        // Online softmax (fp32)
        #pragma unroll
        for (int mt = 0; mt < 2; mt++) {
            #pragma unroll
            for (int hf = 0; hf < 2; hf++) {
                float mx = -1e30f;
                #pragma unroll
                for (int nt = 0; nt < 8; nt++) {
                    mx = fmaxf(mx, sacc[mt][nt][hf * 2]);
                    mx = fmaxf(mx, sacc[mt][nt][hf * 2 + 1]);
                }
                mx = fmaxf(mx, __shfl_xor_sync(0xffffffffu, mx, 1));
                mx = fmaxf(mx, __shfl_xor_sync(0xffffffffu, mx, 2));
                float mn = fmaxf(m_[mt][hf], mx);
                float alpha = __expf(m_[mt][hf] - mn);
                m_[mt][hf] = mn;
                float rs = 0.f;
                #pragma unroll
                for (int nt = 0; nt < 8; nt++) {
                    float p0 = __expf(sacc[mt][nt][hf * 2]     - mn);
                    float p1 = __expf(sacc[mt][nt][hf * 2 + 1] - mn);
                    sacc[mt][nt][hf * 2]     = p0;
                    sacc[mt][nt][hf * 2 + 1] = p1;
                    rs += p0 + p1;
                }
                rs += __shfl_xor_sync(0xffffffffu, rs, 1);
                rs += __shfl_xor_sync(0xffffffffu, rs, 2);
                l_[mt][hf] = l_[mt][hf] * alpha + rs;
                #pragma unroll
                for (int nt = 0; nt < 8; nt++) {
                    oacc[mt][nt][hf * 2]     *= alpha;
                    oacc[mt][nt][hf * 2 + 1] *= alpha;
                }
            }
        }

        // Stage P to smem as half2 (swizzled word stores)
        #pragma unroll
        for (int mt = 0; mt < 2; mt++) {
            int r0 = wm + mt * 16 + gid;
            #pragma unroll
            for (int nt = 0; nt < 8; nt++) {
                uint32_t wc = (uint32_t)((nt * 4 + tig) ^ (gid << 2)) << 2;
                *(__half2*)(sma + 32768 + r0 * 128 + wc) =
                    __floats2half2_rn(sacc[mt][nt][0], sacc[mt][nt][1]);
                *(__half2*)(sma + 32768 + (r0 + 8) * 128 + wc) =
                    __floats2half2_rn(sacc[mt][nt][2], sacc[mt][nt][3]);
            }
        }
        __syncthreads();

        // O += P @ V  (V transposed at read via ldmatrix.trans)
        #pragma unroll
        for (int g = 0; g < 4; g++) {
            uint32_t ap[2][4];
            #pragma unroll
            for (int mt = 0; mt < 2; mt++) {
                int row = wm + mt * 16 + ((bsel & 1) << 3) + lrow;
                int ch  = g * 2 + (bsel >> 1);
                LDSM_X4(ap[mt][0], ap[mt][1], ap[mt][2], ap[mt][3],
                        uP + tile_off(row, ch));
            }
            uint32_t bv[8][2];
            #pragma unroll
            for (int np = 0; np < 4; np++) {
                int key = g * 16 + ((bsel & 1) << 3) + lrow;
                int ch  = 2 * np + (bsel >> 1);
                uint32_t r0, r1, r2, r3;
                LDSM_X4_T(r0, r1, r2, r3, uV + tile_off(key, ch));
                bv[2*np][0] = r0;  bv[2*np][1] = r1;
                bv[2*np+1][0] = r2; bv[2*np+1][1] = r3;
            }
            #pragma unroll
            for (int mt = 0; mt < 2; mt++)
                #pragma unroll
                for (int nt = 0; nt < 8; nt++)
                    mma_f16(oacc[mt][nt], ap[mt], bv[nt]);
        }
    }

    // Epilogue: normalize, half2 store
    #pragma unroll
    for (int mt = 0; mt < 2; mt++) {
        float inv0 = 1.f / l_[mt][0];
        float inv1 = 1.f / l_[mt][1];
        int r0 = q0 + wm + mt * 16 + gid;
        #pragma unroll
        for (int nt = 0; nt < 8; nt++) {
            int cc = h * DHEAD + nt * 8 + tig * 2;
            *(__half2*)&o[((size_t)(b * SEQ + r0)) * INNER + cc] =
                __floats2half2_rn(oacc[mt][nt][0] * inv0, oacc[mt][nt][1] * inv0);
            *(__half2*)&o[((size_t)(b * SEQ + r0 + 8)) * INNER + cc] =
                __floats2half2_rn(oacc[mt][nt][2] * inv1, oacc[mt][nt][3] * inv1);
        }
    }
}

// ----------------------------------------------------------------------------
// Launch
// ----------------------------------------------------------------------------
extern "C" void kernel_launch(void* const* d_in, const int* in_sizes, int n_in,
                              void* d_out, int out_size) {
    const float* x     = (const float*)d_in[0];
    const float* w_q   = (const float*)d_in[1];
    const float* w_kv  = (const float*)d_in[2];
    const float* w_out = (const float*)d_in[3];
    const float* b_out = (const float*)d_in[4];
    const float* gamma = (const float*)d_in[5];
    const float* beta  = (const float*)d_in[6];
    float* out = (float*)d_out;

    void *p_xn, *p_qkv, *p_attn, *p_wqkvT, *p_woutT;
    cudaGetSymbolAddress(&p_xn,    g_xn);
    cudaGetSymbolAddress(&p_qkv,   g_qkv);
    cudaGetSymbolAddress(&p_attn,  g_attn);
    cudaGetSymbolAddress(&p_wqkvT, g_wqkvT);
    cudaGetSymbolAddress(&p_woutT, g_woutT);
    __half* xn    = (__half*)p_xn;
    __half* qkv   = (__half*)p_qkv;
    __half* attn  = (__half*)p_attn;
    __half* wqkvT = (__half*)p_wqkvT;
    __half* woutT = (__half*)p_woutT;

    cudaFuncSetAttribute(attn_f16_kernel,
                         cudaFuncAttributeMaxDynamicSharedMemorySize, ATTN_SMEM);
    cudaFuncSetAttribute(gemm_f16_kernel,
                         cudaFuncAttributeMaxDynamicSharedMemorySize, GEMM_SMEM);

    // 0) Weight transposes (+ fp16 round). ATT_SCALE folded into w_q (exact 2^-3).
    transpose_f16_kernel<<<dim3(INNER/32,   DIM/32), dim3(32, 8)>>>(
        w_q,  wqkvT,               DIM, INNER, ATT_SCALE);
    transpose_f16_kernel<<<dim3(2*INNER/32, DIM/32), dim3(32, 8)>>>(
        w_kv, wqkvT + INNER * DIM, DIM, 2*INNER, 1.0f);
    transpose_f16_kernel<<<dim3(DIM/32,   INNER/32), dim3(32, 8)>>>(
        w_out, woutT, INNER, DIM, 1.0f);

    // 1) LayerNorm (fp16 output)
    ln_kernel<<<ROWS, 256>>>(x, gamma, beta, xn);

    // 2) Fused QKV projection (fp16 mma), N = 3072, half output
    gemm_f16_kernel<<<dim3(QKV_N/128, ROWS/128), 128, GEMM_SMEM>>>(
        xn, wqkvT, qkv, nullptr, nullptr, QKV_N);

    // 3) Flash attention (fp16 mma)
    attn_f16_kernel<<<dim3(SEQ/128, BATCH*HEADS), 128, ATTN_SMEM>>>(qkv, attn);

    // 4) Output projection + bias (fp16 mma), float output
    gemm_f16_kernel<<<dim3(DIM/128, ROWS/128), 128, GEMM_SMEM>>>(
        attn, woutT, nullptr, out, b_out, DIM);
}

// round 9
// speedup vs baseline: 2.7702x; 1.0506x over previous
#include <cuda_runtime.h>
#include <cuda_fp16.h>
#include <math.h>
#include <stdint.h>

// ----------------------------------------------------------------------------
// Problem constants
// ----------------------------------------------------------------------------
#define BATCH  2
#define SEQ    2048
#define DIM    1024
#define HEADS  16
#define DHEAD  64
#define INNER  1024
#define ROWS   (BATCH * SEQ)        // 4096
#define GK     1024
#define QKV_N  3072
#define ATT_SCALE 0.125f

// Scratch (device globals)
__device__ __half g_xn   [ROWS * DIM];        // layernormed x (fp16)
__device__ __half g_qkv  [ROWS * QKV_N];      // q|k|v (fp16; q pre-scaled)
__device__ __half g_attn [ROWS * INNER];      // attention out (fp16)
__device__ __half g_wqkvT[QKV_N * DIM];       // [wq*scale|wkv]^T (fp16)
__device__ __half g_woutT[DIM * INNER];       // w_out^T (fp16)

// ----------------------------------------------------------------------------
// Helpers
// ----------------------------------------------------------------------------
__device__ __forceinline__ uint32_t smem_u32(const void* p) {
    uint32_t a;
    asm("{ .reg .u64 t; cvta.to.shared.u64 t, %1; cvt.u32.u64 %0, t; }"
        : "=r"(a) : "l"(p));
    return a;
}

#define CP_ASYNC16(dst, src) \
    asm volatile("cp.async.cg.shared.global [%0], [%1], 16;" \
                 :: "r"(dst), "l"(src) : "memory")
#define CP_COMMIT() asm volatile("cp.async.commit_group;" ::: "memory")
#define CP_WAIT(n)  asm volatile("cp.async.wait_group %0;" :: "n"(n) : "memory")

#define LDSM_X4(r0, r1, r2, r3, addr) \
    asm volatile("ldmatrix.sync.aligned.m8n8.x4.shared.b16 {%0,%1,%2,%3}, [%4];" \
                 : "=r"(r0), "=r"(r1), "=r"(r2), "=r"(r3) : "r"(addr))
#define LDSM_X4_T(r0, r1, r2, r3, addr) \
    asm volatile("ldmatrix.sync.aligned.m8n8.x4.trans.shared.b16 {%0,%1,%2,%3}, [%4];" \
                 : "=r"(r0), "=r"(r1), "=r"(r2), "=r"(r3) : "r"(addr))

// m16n8k16 fp16 mma, fp32 accumulate
__device__ __forceinline__ void mma_f16(float* d, const uint32_t* a,
                                        const uint32_t* b) {
    asm volatile(
        "mma.sync.aligned.m16n8k16.row.col.f32.f16.f16.f32 "
        "{%0,%1,%2,%3}, {%4,%5,%6,%7}, {%8,%9}, {%0,%1,%2,%3};"
        : "+f"(d[0]), "+f"(d[1]), "+f"(d[2]), "+f"(d[3])
        : "r"(a[0]), "r"(a[1]), "r"(a[2]), "r"(a[3]), "r"(b[0]), "r"(b[1]));
}

// Tiles: rows of 64 halves (128 B). 16B-chunk swizzle: chunk' = chunk ^ (row&7).
__device__ __forceinline__ uint32_t tile_off(int row, int chunk) {
    return (uint32_t)(row * 128 + ((chunk ^ (row & 7)) << 4));
}

// ----------------------------------------------------------------------------
// LayerNorm (fp16 output) — unchanged
// ----------------------------------------------------------------------------
__global__ void ln_kernel(const float* __restrict__ x,
                          const float* __restrict__ gamma,
                          const float* __restrict__ beta,
                          __half* __restrict__ xn) {
    int row = blockIdx.x;
    int t   = threadIdx.x;
    const float* xr = x + (size_t)row * DIM;

    float4 v = *(const float4*)&xr[t * 4];
    float s  = v.x + v.y + v.z + v.w;
    float s2 = v.x*v.x + v.y*v.y + v.z*v.z + v.w*v.w;
    #pragma unroll
    for (int o = 16; o; o >>= 1) {
        s  += __shfl_xor_sync(0xffffffffu, s,  o);
        s2 += __shfl_xor_sync(0xffffffffu, s2, o);
    }
    __shared__ float sh1[8], sh2[8];
    int w = t >> 5, l = t & 31;
    if (l == 0) { sh1[w] = s; sh2[w] = s2; }
    __syncthreads();
    float ts = 0.f, ts2 = 0.f;
    #pragma unroll
    for (int i = 0; i < 8; i++) { ts += sh1[i]; ts2 += sh2[i]; }

    float mean = ts * (1.0f / DIM);
    float var  = ts2 * (1.0f / DIM) - mean * mean;
    float rstd = rsqrtf(var + 1e-5f);

    float4 g  = *(const float4*)&gamma[t * 4];
    float4 bb = *(const float4*)&beta[t * 4];
    __half2 h01 = __floats2half2_rn((v.x - mean) * rstd * g.x + bb.x,
                                    (v.y - mean) * rstd * g.y + bb.y);
    __half2 h23 = __floats2half2_rn((v.z - mean) * rstd * g.z + bb.z,
                                    (v.w - mean) * rstd * g.w + bb.w);
    uint2 pk;
    pk.x = *(uint32_t*)&h01;
    pk.y = *(uint32_t*)&h23;
    *(uint2*)&xn[(size_t)row * DIM + t * 4] = pk;
}

// ----------------------------------------------------------------------------
// Fused weight transposes (+ fp16 round, scale): one launch, z selects section
//   z=0: wq   [1024,1024] -> wqkvT[0],        scale 0.125
//   z=1: wkv  [1024,2048] -> wqkvT[1024*1024], scale 1
//   z=2: wout [1024,1024] -> woutT,            scale 1
// ----------------------------------------------------------------------------
__global__ void transpose_all_kernel(const float* __restrict__ wq,
                                     const float* __restrict__ wkv,
                                     const float* __restrict__ wout,
                                     __half* __restrict__ wqkvT,
                                     __half* __restrict__ woutT) {
    int z = blockIdx.z;
    const float* W;
    __half* Wt;
    int N;
    float scale = 1.0f;
    if (z == 0)      { W = wq;   Wt = wqkvT;                    N = 1024; scale = ATT_SCALE; }
    else if (z == 1) { W = wkv;  Wt = wqkvT + 1024 * 1024;      N = 2048; }
    else             { W = wout; Wt = woutT;                    N = 1024; }
    const int K = 1024;

    int n0 = blockIdx.x * 32, k0 = blockIdx.y * 32;
    if (n0 >= N) return;
    __shared__ float tile[32][33];
    int tx = threadIdx.x, ty = threadIdx.y;
    #pragma unroll
    for (int i = ty; i < 32; i += 8)
        tile[i][tx] = W[(size_t)(k0 + i) * N + n0 + tx];
    __syncthreads();
    #pragma unroll
    for (int i = ty; i < 32; i += 8)
        Wt[(size_t)(n0 + i) * K + k0 + tx] = __float2half_rn(tile[tx][i] * scale);
}

// ----------------------------------------------------------------------------
// fp16 mma GEMM (unchanged from R8): C[M,N](+bias) = A[M,1024] @ Bt[N,1024]^T
// ----------------------------------------------------------------------------
#define GEMM_SMEM (4 * 16384)
#define CHUNKS (GK / 64)

__global__ __launch_bounds__(128)
void gemm_f16_kernel(const __half* __restrict__ A,
                     const __half* __restrict__ Bt,
                     __half* __restrict__ Ch,
                     float* __restrict__ Cf,
                     const float* __restrict__ bias,
                     int N) {
    extern __shared__ char smg[];
    uint32_t base = smem_u32(smg);
    uint32_t uA[2] = { base,          base + 16384u };
    uint32_t uB[2] = { base + 32768u, base + 49152u };

    int t    = threadIdx.x;
    int lane = t & 31;
    int wid  = t >> 5;
    int wm   = (wid >> 1) * 64;
    int wn   = (wid & 1) * 64;
    int gid  = lane >> 2;
    int tig  = lane & 3;
    int bsel = lane >> 3;
    int lrow = lane & 7;
    int bm   = blockIdx.y * 128;
    int bn   = blockIdx.x * 128;

    const __half* Ag = A  + (size_t)bm * GK;
    const __half* Bg = Bt + (size_t)bn * GK;

    float acc[4][8][4];
    #pragma unroll
    for (int mt = 0; mt < 4; mt++)
        #pragma unroll
        for (int nt = 0; nt < 8; nt++)
            #pragma unroll
            for (int i = 0; i < 4; i++) acc[mt][nt][i] = 0.f;

    auto load_chunk = [&](int c, int s) {
        int k0 = c * 64;
        #pragma unroll
        for (int i = 0; i < 8; ++i) {
            int idx = t + i * 128;
            int row = idx >> 3, q = idx & 7;
            CP_ASYNC16(uA[s] + tile_off(row, q),
                       Ag + (size_t)row * GK + k0 + q * 8);
        }
        #pragma unroll
        for (int i = 0; i < 8; ++i) {
            int idx = t + i * 128;
            int row = idx >> 3, q = idx & 7;
            CP_ASYNC16(uB[s] + tile_off(row, q),
                       Bg + (size_t)row * GK + k0 + q * 8);
        }
        CP_COMMIT();
    };

    load_chunk(0, 0);
    load_chunk(1, 1);

    for (int c = 0; c < CHUNKS; ++c) {
        int s = c & 1;
        if (c == CHUNKS - 1) { CP_WAIT(0); } else { CP_WAIT(1); }
        __syncthreads();

        #pragma unroll
        for (int g = 0; g < 4; ++g) {
            uint32_t af[4][4];
            #pragma unroll
            for (int mt = 0; mt < 4; mt++) {
                int row = wm + mt * 16 + ((bsel & 1) << 3) + lrow;
                int ch  = g * 2 + (bsel >> 1);
                LDSM_X4(af[mt][0], af[mt][1], af[mt][2], af[mt][3],
                        uA[s] + tile_off(row, ch));
            }
            uint32_t bf[8][2];
            #pragma unroll
            for (int np = 0; np < 4; np++) {
                int nrow = wn + ((2 * np + (bsel >> 1)) << 3) + lrow;
                int ch   = g * 2 + (bsel & 1);
                uint32_t r0, r1, r2, r3;
                LDSM_X4(r0, r1, r2, r3, uB[s] + tile_off(nrow, ch));
                bf[2*np][0] = r0;  bf[2*np][1] = r1;
                bf[2*np+1][0] = r2; bf[2*np+1][1] = r3;
            }
            #pragma unroll
            for (int mt = 0; mt < 4; mt++)
                #pragma unroll
                for (int nt = 0; nt < 8; nt++)
                    mma_f16(acc[mt][nt], af[mt], bf[nt]);
        }
        __syncthreads();
        if (c + 2 < CHUNKS) load_chunk(c + 2, s);
    }

    #pragma unroll
    for (int mt = 0; mt < 4; mt++) {
        int r0 = bm + wm + mt * 16 + gid;
        #pragma unroll
        for (int nt = 0; nt < 8; nt++) {
            int cc = bn + wn + nt * 8 + tig * 2;
            float b0 = bias ? bias[cc]     : 0.f;
            float b1 = bias ? bias[cc + 1] : 0.f;
            if (Ch) {
                *(__half2*)&Ch[(size_t)r0 * N + cc] =
                    __floats2half2_rn(acc[mt][nt][0] + b0, acc[mt][nt][1] + b1);
                *(__half2*)&Ch[(size_t)(r0 + 8) * N + cc] =
                    __floats2half2_rn(acc[mt][nt][2] + b0, acc[mt][nt][3] + b1);
            } else {
                *(float2*)&Cf[(size_t)r0 * N + cc] =
                    make_float2(acc[mt][nt][0] + b0, acc[mt][nt][1] + b1);
                *(float2*)&Cf[(size_t)(r0 + 8) * N + cc] =
                    make_float2(acc[mt][nt][2] + b0, acc[mt][nt][3] + b1);
            }
        }
    }
}

// ----------------------------------------------------------------------------
// Flash attention, fp16 mma, cp.async double-buffered K/V.
// Smem (64KB): Q[128][64]h @0, P[128][64]h @16K,
//              K0 @32K, K1 @40K, V0 @48K, V1 @56K (each 64x64 h = 8KB).
// ----------------------------------------------------------------------------
#define ATTN_SMEM 65536

__global__ __launch_bounds__(128) void attn_f16_kernel(
    const __half* __restrict__ qkv, __half* __restrict__ o) {
    extern __shared__ char sma[];
    uint32_t uQ = smem_u32(sma);
    uint32_t uP = uQ + 16384u;
    uint32_t uK[2] = { uQ + 32768u, uQ + 40960u };
    uint32_t uV[2] = { uQ + 49152u, uQ + 57344u };

    int bh = blockIdx.y;
    int b  = bh >> 4, h = bh & 15;
    int q0 = blockIdx.x * 128;
    int t  = threadIdx.x;
    int lane = t & 31, w = t >> 5;
    int gid = lane >> 2, tig = lane & 3;
    int bsel = lane >> 3, lrow = lane & 7;
    int wm  = w * 32;

    // Load Q tile (plain stores; visible after first __syncthreads)
    #pragma unroll
    for (int i = 0; i < 8; i++) {
        int idx = i * 128 + t;
        int r = idx >> 3, q = idx & 7;
        *(uint4*)(sma + tile_off(r, q)) =
            *(const uint4*)(qkv + ((size_t)(b * SEQ + q0 + r)) * QKV_N
                            + h * DHEAD + q * 8);
    }

    // K/V tile prefetch via cp.async (8 cp per thread per tile)
    auto load_kv = [&](int j0, int s) {
        #pragma unroll
        for (int i = 0; i < 4; i++) {
            int idx = i * 128 + t;
            int r = idx >> 3, q = idx & 7;
            size_t gb = ((size_t)(b * SEQ + j0 + r)) * QKV_N + h * DHEAD + q * 8;
            uint32_t off = tile_off(r, q);
            CP_ASYNC16(uK[s] + off, qkv + gb + INNER);
            CP_ASYNC16(uV[s] + off, qkv + gb + 2 * INNER);
        }
        CP_COMMIT();
    };

    load_kv(0, 0);

    float m_[2][2], l_[2][2], oacc[2][8][4];
    #pragma unroll
    for (int mt = 0; mt < 2; mt++)
        #pragma unroll
        for (int hf = 0; hf < 2; hf++) { m_[mt][hf] = -1e30f; l_[mt][hf] = 0.f; }
    #pragma unroll
    for (int mt = 0; mt < 2; mt++)
        #pragma unroll
        for (int nt = 0; nt < 8; nt++)
            #pragma unroll
            for (int i = 0; i < 4; i++) oacc[mt][nt][i] = 0.f;

    for (int j = 0; j < SEQ / 64; j++) {
        int s = j & 1;
        CP_WAIT(0);            // tile j resident
        __syncthreads();       // + all warps done reading buffer s^1 (iter j-1)
        if (j + 1 < SEQ / 64) load_kv((j + 1) * 64, s ^ 1);  // overlaps compute

        // S = Q @ K^T
        float sacc[2][8][4];
        #pragma unroll
        for (int mt = 0; mt < 2; mt++)
            #pragma unroll
            for (int nt = 0; nt < 8; nt++)
                #pragma unroll
                for (int i = 0; i < 4; i++) sacc[mt][nt][i] = 0.f;

        #pragma unroll
        for (int g = 0; g < 4; g++) {
            uint32_t aq[2][4];
            #pragma unroll
            for (int mt = 0; mt < 2; mt++) {
                int row = wm + mt * 16 + ((bsel & 1) << 3) + lrow;
                int ch  = g * 2 + (bsel >> 1);
                LDSM_X4(aq[mt][0], aq[mt][1], aq[mt][2], aq[mt][3],
                        uQ + tile_off(row, ch));
            }
            uint32_t bk[8][2];
            #pragma unroll
            for (int np = 0; np < 4; np++) {
                int nrow = ((2 * np + (bsel >> 1)) << 3) + lrow;
                int ch   = g * 2 + (bsel & 1);
                uint32_t r0, r1, r2, r3;
                LDSM_X4(r0, r1, r2, r3, uK[s] + tile_off(nrow, ch));
                bk[2*np][0] = r0;  bk[2*np][1] = r1;
                bk[2*np+1][0] = r2; bk[2*np+1][1] = r3;
            }
            #pragma unroll
            for (int mt = 0; mt < 2; mt++)
                #pragma unroll
                for (int nt = 0; nt < 8; nt++)
                    mma_f16(sacc[mt][nt], aq[mt], bk[nt]);
        }

        // Online softmax (fp32)
        #pragma unroll
        for (int mt = 0; mt < 2; mt++) {
            #pragma unroll
            for (int hf = 0; hf < 2; hf++) {
                float mx = -1e30f;
                #pragma unroll
                for (int nt = 0; nt < 8; nt++) {
                    mx = fmaxf(mx, sacc[mt][nt][hf * 2]);
                    mx = fmaxf(mx, sacc[mt][nt][hf * 2 + 1]);
                }
                mx = fmaxf(mx, __shfl_xor_sync(0xffffffffu, mx, 1));
                mx = fmaxf(mx, __shfl_xor_sync(0xffffffffu, mx, 2));
                float mn = fmaxf(m_[mt][hf], mx);
                float alpha = __expf(m_[mt][hf] - mn);
                m_[mt][hf] = mn;
                float rs = 0.f;
                #pragma unroll
                for (int nt = 0; nt < 8; nt++) {
                    float p0 = __expf(sacc[mt][nt][hf * 2]     - mn);
                    float p1 = __expf(sacc[mt][nt][hf * 2 + 1] - mn);
                    sacc[mt][nt][hf * 2]     = p0;
                    sacc[mt][nt][hf * 2 + 1] = p1;
                    rs += p0 + p1;
                }
                rs += __shfl_xor_sync(0xffffffffu, rs, 1);
                rs += __shfl_xor_sync(0xffffffffu, rs, 2);
                l_[mt][hf] = l_[mt][hf] * alpha + rs;
                #pragma unroll
                for (int nt = 0; nt < 8; nt++) {
                    oacc[mt][nt][hf * 2]     *= alpha;
                    oacc[mt][nt][hf * 2 + 1] *= alpha;
                }
            }
        }

        // Stage P to smem as half2 (swizzled word stores)
        #pragma unroll
        for (int mt = 0; mt < 2; mt++) {
            int r0 = wm + mt * 16 + gid;
            #pragma unroll
            for (int nt = 0; nt < 8; nt++) {
                uint32_t wc = (uint32_t)((nt * 4 + tig) ^ (gid << 2)) << 2;
                *(__half2*)(sma + 16384 + r0 * 128 + wc) =
                    __floats2half2_rn(sacc[mt][nt][0], sacc[mt][nt][1]);
                *(__half2*)(sma + 16384 + (r0 + 8) * 128 + wc) =
                    __floats2half2_rn(sacc[mt][nt][2], sacc[mt][nt][3]);
            }
        }
        __syncthreads();

        // O += P @ V  (V transposed at read via ldmatrix.trans)
        #pragma unroll
        for (int g = 0; g < 4; g++) {
            uint32_t ap[2][4];
            #pragma unroll
            for (int mt = 0; mt < 2; mt++) {
                int row = wm + mt * 16 + ((bsel & 1) << 3) + lrow;
                int ch  = g * 2 + (bsel >> 1);
                LDSM_X4(ap[mt][0], ap[mt][1], ap[mt][2], ap[mt][3],
                        uP + tile_off(row, ch));
            }
            uint32_t bv[8][2];
            #pragma unroll
            for (int np = 0; np < 4; np++) {
                int key = g * 16 + ((bsel & 1) << 3) + lrow;
                int ch  = 2 * np + (bsel >> 1);
                uint32_t r0, r1, r2, r3;
                LDSM_X4_T(r0, r1, r2, r3, uV[s] + tile_off(key, ch));
                bv[2*np][0] = r0;  bv[2*np][1] = r1;
                bv[2*np+1][0] = r2; bv[2*np+1][1] = r3;
            }
            #pragma unroll
            for (int mt = 0; mt < 2; mt++)
                #pragma unroll
                for (int nt = 0; nt < 8; nt++)
                    mma_f16(oacc[mt][nt], ap[mt], bv[nt]);
        }
    }

    // Epilogue: normalize, half2 store
    #pragma unroll
    for (int mt = 0; mt < 2; mt++) {
        float inv0 = 1.f / l_[mt][0];
        float inv1 = 1.f / l_[mt][1];
        int r0 = q0 + wm + mt * 16 + gid;
        #pragma unroll
        for (int nt = 0; nt < 8; nt++) {
            int cc = h * DHEAD + nt * 8 + tig * 2;
            *(__half2*)&o[((size_t)(b * SEQ + r0)) * INNER + cc] =
                __floats2half2_rn(oacc[mt][nt][0] * inv0, oacc[mt][nt][1] * inv0);
            *(__half2*)&o[((size_t)(b * SEQ + r0 + 8)) * INNER + cc] =
                __floats2half2_rn(oacc[mt][nt][2] * inv1, oacc[mt][nt][3] * inv1);
        }
    }
}

// ----------------------------------------------------------------------------
// Launch
// ----------------------------------------------------------------------------
extern "C" void kernel_launch(void* const* d_in, const int* in_sizes, int n_in,
                              void* d_out, int out_size) {
    const float* x     = (const float*)d_in[0];
    const float* w_q   = (const float*)d_in[1];
    const float* w_kv  = (const float*)d_in[2];
    const float* w_out = (const float*)d_in[3];
    const float* b_out = (const float*)d_in[4];
    const float* gamma = (const float*)d_in[5];
    const float* beta  = (const float*)d_in[6];
    float* out = (float*)d_out;

    void *p_xn, *p_qkv, *p_attn, *p_wqkvT, *p_woutT;
    cudaGetSymbolAddress(&p_xn,    g_xn);
    cudaGetSymbolAddress(&p_qkv,   g_qkv);
    cudaGetSymbolAddress(&p_attn,  g_attn);
    cudaGetSymbolAddress(&p_wqkvT, g_wqkvT);
    cudaGetSymbolAddress(&p_woutT, g_woutT);
    __half* xn    = (__half*)p_xn;
    __half* qkv   = (__half*)p_qkv;
    __half* attn  = (__half*)p_attn;
    __half* wqkvT = (__half*)p_wqkvT;
    __half* woutT = (__half*)p_woutT;

    cudaFuncSetAttribute(attn_f16_kernel,
                         cudaFuncAttributeMaxDynamicSharedMemorySize, ATTN_SMEM);
    cudaFuncSetAttribute(gemm_f16_kernel,
                         cudaFuncAttributeMaxDynamicSharedMemorySize, GEMM_SMEM);

    // 0) Fused weight transposes (+ fp16 round, wq pre-scaled by 0.125)
    transpose_all_kernel<<<dim3(64, 32, 3), dim3(32, 8)>>>(
        w_q, w_kv, w_out, wqkvT, woutT);

    // 1) LayerNorm (fp16 output)
    ln_kernel<<<ROWS, 256>>>(x, gamma, beta, xn);

    // 2) Fused QKV projection (fp16 mma), N = 3072, half output
    gemm_f16_kernel<<<dim3(QKV_N/128, ROWS/128), 128, GEMM_SMEM>>>(
        xn, wqkvT, qkv, nullptr, nullptr, QKV_N);

    // 3) Flash attention (fp16 mma, cp.async double-buffered KV)
    attn_f16_kernel<<<dim3(SEQ/128, BATCH*HEADS), 128, ATTN_SMEM>>>(qkv, attn);

    // 4) Output projection + bias (fp16 mma), float output
    gemm_f16_kernel<<<dim3(DIM/128, ROWS/128), 128, GEMM_SMEM>>>(
        attn, woutT, nullptr, out, b_out, DIM);
}